// round 12
// baseline (speedup 1.0000x reference)
#include <cuda_runtime.h>
#include <cuda_fp16.h>
#include <cstdint>

// Shapes (fixed)
#define NB 4
#define NQ 512
#define NK 512
#define ND 256
#define NH 256

__device__ float  g_qh[NB * NQ * NH];    // projected queries, f32, row-major
__device__ __half g_khT[NB * NH * NK];   // projected keys, f16, TRANSPOSED [b][h][key]

__device__ __forceinline__ unsigned hadd2_u(unsigned a, unsigned b) {
    unsigned r; asm("add.rn.f16x2 %0, %1, %2;" : "=r"(r) : "r"(a), "r"(b)); return r;
}
__device__ __forceinline__ unsigned tanh2_u(unsigned x) {
    unsigned r; asm("tanh.approx.f16x2 %0, %1;" : "=r"(r) : "r"(x)); return r;
}
__device__ __forceinline__ unsigned hfma2_u(unsigned a, unsigned b, unsigned c) {
    unsigned r; asm("fma.rn.f16x2 %0, %1, %2, %3;" : "=r"(r) : "r"(a), "r"(b), "r"(c)); return r;
}
__device__ __forceinline__ float2 h2f2(unsigned h) {
    __half2 hh = *reinterpret_cast<__half2*>(&h);
    return __half22float2(hh);
}
__device__ __forceinline__ unsigned f2h2(float lo, float hi) {
    __half2 hh = __floats2half2_rn(lo, hi);
    return *reinterpret_cast<unsigned*>(&hh);
}

// ---------------------------------------------------------------------------
// Projection GEMM: C[2048x256] = A[2048x256] @ W[256x256]
// z = 0 -> g_qh (f32, row-major); z = 1 -> g_khT (f16, TRANSPOSED via smem)
// ---------------------------------------------------------------------------
__global__ __launch_bounds__(256) void proj_kernel(
    const float* __restrict__ Aq, const float* __restrict__ Wq,
    const float* __restrict__ Ak, const float* __restrict__ Wk)
{
    const float* A; const float* W;
    if (blockIdx.z == 0) { A = Aq; W = Wq; }
    else                 { A = Ak; W = Wk; }

    __shared__ float sraw[2 * 16 * 68];            // As | Bs; reused for transpose
    float* As = sraw;                              // [16][68]
    float* Bs = sraw + 16 * 68;                    // [16][68]

    const int t    = threadIdx.x;
    const int row0 = blockIdx.y * 64;
    const int col0 = blockIdx.x * 64;
    const int ty   = t >> 4;
    const int tx   = t & 15;

    float acc[4][4] = {};

    for (int k0 = 0; k0 < ND; k0 += 16) {
        {
            int r  = t >> 2;
            int c4 = (t & 3) * 4;
            float4 v = *(const float4*)&A[(row0 + r) * ND + k0 + c4];
            As[(c4 + 0) * 68 + r] = v.x;
            As[(c4 + 1) * 68 + r] = v.y;
            As[(c4 + 2) * 68 + r] = v.z;
            As[(c4 + 3) * 68 + r] = v.w;
        }
        {
            int r  = t >> 4;
            int c4 = (t & 15) * 4;
            *(float4*)&Bs[r * 68 + c4] = *(const float4*)&W[(k0 + r) * NH + col0 + c4];
        }
        __syncthreads();
        #pragma unroll
        for (int kk = 0; kk < 16; kk++) {
            float4 av = *(float4*)&As[kk * 68 + ty * 4];
            float4 bv = *(float4*)&Bs[kk * 68 + tx * 4];
            float a_[4] = {av.x, av.y, av.z, av.w};
            float b_[4] = {bv.x, bv.y, bv.z, bv.w};
            #pragma unroll
            for (int i = 0; i < 4; i++)
                #pragma unroll
                for (int j = 0; j < 4; j++)
                    acc[i][j] += a_[i] * b_[j];
        }
        __syncthreads();
    }

    if (blockIdx.z == 0) {
        #pragma unroll
        for (int i = 0; i < 4; i++) {
            float4 v = make_float4(acc[i][0], acc[i][1], acc[i][2], acc[i][3]);
            *(float4*)&g_qh[(row0 + ty * 4 + i) * NH + col0 + tx * 4] = v;
        }
    } else {
        // transpose 64x64 tile through smem, emit f16 to g_khT[b][h][key]
        __half* ts = (__half*)sraw;                // 64 x 68 halfs = 8704 B (fits)
        #pragma unroll
        for (int i = 0; i < 4; i++) {
            uint2 u;
            u.x = f2h2(acc[i][0], acc[i][1]);
            u.y = f2h2(acc[i][2], acc[i][3]);
            *(uint2*)&ts[(ty * 4 + i) * 68 + tx * 4] = u;   // ts[key][h]
        }
        __syncthreads();

        const int h  = t & 63;
        const int kg = t >> 6;                     // 4 groups of 16 keys
        const int b2     = row0 >> 9;              // batch (keys 512-aligned per batch)
        const int rowInB = row0 & 511;

        uint4 pk[2];
        __half* tmp = (__half*)pk;
        #pragma unroll
        for (int kk = 0; kk < 16; kk++)
            tmp[kk] = ts[(kg * 16 + kk) * 68 + h];

        __half* dst = &g_khT[((size_t)(b2 * NH + col0 + h)) * NK + rowInB + kg * 16];
        *(uint4*)dst       = pk[0];
        *(uint4*)(dst + 8) = pk[1];
    }
}

// ---------------------------------------------------------------------------
// Fused attention, transposed-f16x2 Phase A:
//  - tile = 64 keys x 256 h of g_khT in smem as f16x2 key-pairs: tile[h][32]
//  - lane = key-pair; per h-step: LDS kv + LDS.64 {q2,wv2} + HADD2 + TANH2 +
//    HFMA2  (~5 instrs / 64 elems, NO reduction shuffles)
//  - f16x2 accumulation in 4 chains, drained to f32 every 16 h-steps
//  - Phase C: f32 values (R1 style)
// 512 blocks x 128 threads = 4 warps = 4 queries of batch (blockIdx & 3).
// ---------------------------------------------------------------------------
__global__ __launch_bounds__(128) void attn_kernel(
    const float* __restrict__ values,
    const float* __restrict__ wv,
    const int*   __restrict__ valid_lens,
    float*       __restrict__ out)
{
    extern __shared__ char smem[];
    unsigned* tile   = (unsigned*)smem;            // A: [256][32] f16x2  (32768 B)
    float*    vtile  = (float*)smem;               // C: [16][260] f32    (16640 B)
    uint2*    s_qw   = (uint2*)(smem + 32768);     // [4][256] {q2, wv2}  (8192 B)
    float*    attn_s = (float*)(smem + 40960);     // [4][512]            (8192 B)

    const int t    = threadIdx.x;
    const int w    = t >> 5;                       // warp = query
    const int lane = t & 31;                       // key-pair in group
    const int b    = blockIdx.x & 3;               // batch-interleaved
    const int qblk = blockIdx.x >> 2;              // 0..127
    const int vl   = valid_lens[b];                // uniform across block
    const int qrow = b * NQ + qblk * 4 + w;

    // ---------------- prep s_qw: duplicated f16x2 of q[h] and wv[h] --------
    {
        const float* qp = &g_qh[(size_t)qrow * NH];
        #pragma unroll
        for (int i = 0; i < 8; i++) {
            int h = lane + 32 * i;
            float qv  = qp[h];
            float wvv = wv[h];
            uint2 e;
            e.x = f2h2(qv, qv);
            e.y = f2h2(wvv, wvv);
            s_qw[w * 256 + h] = e;
        }
    }

    // ---------------- Phase A: scores -> attn_s ----------------
    const uint4* ksrc = (const uint4*)&g_khT[(size_t)b * NH * NK];  // [256][64] uint4
    const int ng = (vl + 63) >> 6;

    for (int g = 0; g < ng; ++g) {
        __syncthreads();                           // prev tile reads done (+ s_qw on g=0)
        // stage 64 keys x 256 h: 2048 uint4, 16/thread
        #pragma unroll
        for (int r = 0; r < 16; ++r) {
            int i   = t + 128 * r;
            int row = i >> 3;                      // h
            int c   = i & 7;
            ((uint4*)tile)[row * 8 + c] = ksrc[row * 64 + g * 8 + c];
        }
        __syncthreads();

        float sc0 = 0.f, sc1 = 0.f;
        for (int h0 = 0; h0 < 256; h0 += 16) {
            unsigned acc[4] = {0u, 0u, 0u, 0u};
            #pragma unroll
            for (int hw = 0; hw < 16; ++hw) {
                int h = h0 + hw;
                unsigned kv = tile[h * 32 + lane];         // 2 keys at h
                uint2 qw = s_qw[w * 256 + h];              // broadcast
                unsigned x  = hadd2_u(kv, qw.x);
                unsigned th = tanh2_u(x);
                acc[hw & 3] = hfma2_u(qw.y, th, acc[hw & 3]);
            }
            #pragma unroll
            for (int c = 0; c < 4; c++) {
                float2 f = h2f2(acc[c]);
                sc0 += f.x; sc1 += f.y;
            }
        }
        attn_s[w * NK + g * 64 + 2 * lane]     = sc0;      // key 2*lane
        attn_s[w * NK + g * 64 + 2 * lane + 1] = sc1;      // key 2*lane+1
    }
    __syncthreads();                               // scores visible within warps

    // ---------------- Phase B: masked softmax (warp = query) ----------------
    float mx = -1.0e30f;
    for (int i = 0; i < 16; i++) {
        int k = i * 32 + lane;
        float v = (k < vl) ? attn_s[w * NK + k] : -1.0e6f;
        mx = fmaxf(mx, v);
    }
    #pragma unroll
    for (int o = 16; o > 0; o >>= 1)
        mx = fmaxf(mx, __shfl_xor_sync(0xffffffffu, mx, o));

    float sum = 0.f;
    for (int i = 0; i < 16; i++) {
        int k = i * 32 + lane;
        float v = (k < vl) ? attn_s[w * NK + k] : -1.0e6f;
        float e = __expf(v - mx);                  // masked -> exact 0
        sum += e;
        attn_s[w * NK + k] = e;                    // unnormalized (warp-own row)
    }
    #pragma unroll
    for (int o = 16; o > 0; o >>= 1)
        sum += __shfl_xor_sync(0xffffffffu, sum, o);
    const float inv = 1.0f / sum;

    // ---------------- Phase C: out = attn @ values (f32) --------------------
    const float* vb = &values[(size_t)(b * NK) * ND];
    const int nTC = (vl + 15) >> 4;
    float4 o0 = make_float4(0.f, 0.f, 0.f, 0.f);
    float4 o1 = make_float4(0.f, 0.f, 0.f, 0.f);

    for (int tl = 0; tl < nTC; ++tl) {
        __syncthreads();                           // prev tile reads done
        // stage 16 keys x 256 d: 1024 float4, 8/thread
        #pragma unroll
        for (int r = 0; r < 8; ++r) {
            int i   = t + 128 * r;
            int row = i >> 6;
            int c4  = (i & 63) * 4;
            *(float4*)&vtile[row * 260 + c4] =
                *(const float4*)&vb[(tl * 16 + row) * ND + c4];
        }
        __syncthreads();

        #pragma unroll 4
        for (int kk = 0; kk < 16; ++kk) {
            float a = attn_s[w * NK + tl * 16 + kk];       // broadcast (own row)
            float4 v0 = *(const float4*)&vtile[kk * 260 + 4 * lane];
            float4 v1 = *(const float4*)&vtile[kk * 260 + 128 + 4 * lane];
            o0.x += a * v0.x; o0.y += a * v0.y; o0.z += a * v0.z; o0.w += a * v0.w;
            o1.x += a * v1.x; o1.y += a * v1.y; o1.z += a * v1.z; o1.w += a * v1.w;
        }
    }

    o0.x *= inv; o0.y *= inv; o0.z *= inv; o0.w *= inv;
    o1.x *= inv; o1.y *= inv; o1.z *= inv; o1.w *= inv;
    *(float4*)&out[(size_t)qrow * ND + 4 * lane]       = o0;
    *(float4*)&out[(size_t)qrow * ND + 128 + 4 * lane] = o1;
}

#define ATTN_SMEM 49152

// ---------------------------------------------------------------------------
extern "C" void kernel_launch(void* const* d_in, const int* in_sizes, int n_in,
                              void* d_out, int out_size)
{
    const float* queries = (const float*)d_in[0];
    const float* keys    = (const float*)d_in[1];
    const float* values  = (const float*)d_in[2];
    const float* Wq      = (const float*)d_in[3];
    const float* Wk      = (const float*)d_in[4];
    const float* wv      = (const float*)d_in[5];
    const int*   vlen    = (const int*)d_in[6];
    float* out = (float*)d_out;

    (void)in_sizes; (void)n_in; (void)out_size;

    cudaFuncSetAttribute(attn_kernel,
                         cudaFuncAttributeMaxDynamicSharedMemorySize, ATTN_SMEM);

    dim3 pgrid(NH / 64, (NB * NQ) / 64, 2);
    proj_kernel<<<pgrid, 256>>>(queries, Wq, keys, Wk);

    attn_kernel<<<(NB * NQ) / 4, 128, ATTN_SMEM>>>(values, wv, vlen, out);
}